// round 9
// baseline (speedup 1.0000x reference)
#include <cuda_runtime.h>

// ---------------------------------------------------------------------------
// Quanvolution filter, fully fused single kernel.
//
// Algebra:  <Z_w>(patch) = sum_{t in {I,C,S}^4} coef[w][t] * prod_i f_{t_i}(x_i)
// with f_I = 1, f_C = cos(x_i), f_S = sin(x_i); coef depends only on params.
//
// Every block recomputes the 324 coefficients (cheap: 16x16 unitary built
// amplitude-parallel, A_w = Re(W^H Z_w W), closed-form 16-term expansion)
// directly into shared memory, then evaluates 4 patches/thread with
// wire-pair-packed f32x2 FFMA2 chains (the R5 main loop, measured 14.4us).
// This removes the separate 1-block setup kernel + launch gap (~5us).
// ---------------------------------------------------------------------------

typedef unsigned long long ull;

__device__ __forceinline__ ull ffma2(ull a, ull b, ull c) {
    ull d;
    asm("fma.rn.f32x2 %0, %1, %2, %3;" : "=l"(d) : "l"(a), "l"(b), "l"(c));
    return d;
}
__device__ __forceinline__ ull pack2(float x) {
    ull d;
    asm("mov.b64 %0, {%1, %1};" : "=l"(d) : "f"(x));
    return d;
}
__device__ __forceinline__ void unpack2(ull v, float& lo, float& hi) {
    asm("mov.b64 {%0, %1}, %2;" : "=f"(lo), "=f"(hi) : "l"(v));
}

struct Trig { ull c0, s0, c1, s1, c2, s2, c3, s3; };

__device__ __forceinline__ Trig load_trig(const float* __restrict__ x, int pidx)
{
    const int b   = pidx / 196;
    const int p   = pidx - b * 196;
    const int r   = p / 14;
    const int col = p - r * 14;
    const float* xp = x + b * 784 + r * 56 + col * 2;
    const float2 top = *(const float2*)xp;
    const float2 bot = *(const float2*)(xp + 28);
    float c0, s0, c1, s1, c2, s2, c3, s3;
    __sincosf(top.x, &s0, &c0);
    __sincosf(top.y, &s1, &c1);
    __sincosf(bot.x, &s2, &c2);
    __sincosf(bot.y, &s3, &c3);
    Trig t;
    t.c0 = pack2(c0); t.s0 = pack2(s0);
    t.c1 = pack2(c1); t.s1 = pack2(s1);
    t.c2 = pack2(c2); t.s2 = pack2(s2);
    t.c3 = pack2(c3); t.s3 = pack2(s3);
    return t;
}

__device__ __forceinline__ int cnot_perm(int m) {
    m ^= (m & 1) ? 8 : 0;   // f30
    m ^= (m & 2) ? 1 : 0;   // f23
    m ^= (m & 4) ? 2 : 0;   // f12
    m ^= (m & 8) ? 4 : 0;   // f01
    return m;
}

#define P 4   // patches per thread

__global__ void __launch_bounds__(128)
quanv_fused_kernel(const float* __restrict__ x,
                   const float* __restrict__ params,
                   float* __restrict__ out)
{
    __shared__ float  Gr[8][4];
    __shared__ float  Gi[8][4];
    __shared__ float2 cs[256];     // [j*16 + m]
    __shared__ float  Wr[16][16];  // W[m][j]
    __shared__ float  Wi[16][16];
    __shared__ float  A[4][16][16];
    __shared__ __align__(16) float shc[324];  // shc[q*4 + w]

    const int tid = threadIdx.x;

    // ---- per-block setup: gate matrices G = RX(p2) RZ(p1) RY(p0) ----
    if (tid < 8) {
        const float a = params[tid * 3 + 0] * 0.5f;
        const float b = params[tid * 3 + 1] * 0.5f;
        const float c = params[tid * 3 + 2] * 0.5f;
        float ca, sa, cb, sb, cc, sc;
        __sincosf(a, &sa, &ca);
        __sincosf(b, &sb, &cb);
        __sincosf(c, &sc, &cc);
        const float m00r =  cb * ca, m00i = -sb * ca;
        const float m01r = -cb * sa, m01i =  sb * sa;
        const float m10r =  cb * sa, m10i =  sb * sa;
        const float m11r =  cb * ca, m11i =  sb * ca;
        Gr[tid][0] = cc * m00r + sc * m10i;  Gi[tid][0] = cc * m00i - sc * m10r;
        Gr[tid][1] = cc * m01r + sc * m11i;  Gi[tid][1] = cc * m01i - sc * m11r;
        Gr[tid][2] = cc * m10r + sc * m00i;  Gi[tid][2] = cc * m10i - sc * m00r;
        Gr[tid][3] = cc * m11r + sc * m01i;  Gi[tid][3] = cc * m11i - sc * m01r;
    }
    __syncthreads();

    // ---- amplitude-parallel unitary build: 2 (column, amplitude) slots/thread ----
    {
        const int i0 = tid, i1 = tid + 128;
        const int j0 = i0 >> 4, m0 = i0 & 15;
        const int j1 = i1 >> 4, m1 = i1 & 15;
        float2 sv0 = (m0 == j0) ? make_float2(1.f, 0.f) : make_float2(0.f, 0.f);
        float2 sv1 = (m1 == j1) ? make_float2(1.f, 0.f) : make_float2(0.f, 0.f);

        #pragma unroll
        for (int l = 0; l < 2; l++) {
            #pragma unroll
            for (int w = 0; w < 4; w++) {
                cs[i0] = sv0; cs[i1] = sv1;
                __syncthreads();
                const int mask = 8 >> w;
                const int g = l * 4 + w;
                {
                    const int bsel = (m0 & mask) ? 1 : 0;
                    const float2 a0 = cs[(j0 << 4) | (m0 & ~mask)];
                    const float2 a1 = cs[(j0 << 4) | (m0 |  mask)];
                    const float g0r = Gr[g][bsel * 2 + 0], g0i = Gi[g][bsel * 2 + 0];
                    const float g1r = Gr[g][bsel * 2 + 1], g1i = Gi[g][bsel * 2 + 1];
                    float2 ns;
                    ns.x = g0r * a0.x - g0i * a0.y + g1r * a1.x - g1i * a1.y;
                    ns.y = g0r * a0.y + g0i * a0.x + g1r * a1.y + g1i * a1.x;
                    sv0 = ns;
                }
                {
                    const int bsel = (m1 & mask) ? 1 : 0;
                    const float2 a0 = cs[(j1 << 4) | (m1 & ~mask)];
                    const float2 a1 = cs[(j1 << 4) | (m1 |  mask)];
                    const float g0r = Gr[g][bsel * 2 + 0], g0i = Gi[g][bsel * 2 + 0];
                    const float g1r = Gr[g][bsel * 2 + 1], g1i = Gi[g][bsel * 2 + 1];
                    float2 ns;
                    ns.x = g0r * a0.x - g0i * a0.y + g1r * a1.x - g1i * a1.y;
                    ns.y = g0r * a0.y + g0i * a0.x + g1r * a1.y + g1i * a1.x;
                    sv1 = ns;
                }
                __syncthreads();
            }
            // CNOT ring (0,1)(1,2)(2,3)(3,0) as one composed permutation
            cs[i0] = sv0; cs[i1] = sv1;
            __syncthreads();
            sv0 = cs[(j0 << 4) | cnot_perm(m0)];
            sv1 = cs[(j1 << 4) | cnot_perm(m1)];
            __syncthreads();
        }
        Wr[m0][j0] = sv0.x;  Wi[m0][j0] = sv0.y;
        Wr[m1][j1] = sv1.x;  Wi[m1][j1] = sv1.y;
    }
    __syncthreads();

    // ---- A_w[j][k] = sum_m z_w(m) Re(conj(W[m,j]) W[m,k]), 2 entries/thread ----
    #pragma unroll
    for (int k = 0; k < 2; k++) {
        const int e = tid + k * 128;
        const int jj = e >> 4, kk = e & 15;
        float acc0 = 0.f, acc1 = 0.f, acc2 = 0.f, acc3 = 0.f;
        #pragma unroll
        for (int mm = 0; mm < 16; mm++) {
            const float v = Wr[mm][jj] * Wr[mm][kk] + Wi[mm][jj] * Wi[mm][kk];
            acc0 += ((mm >> 3) & 1) ? -v : v;
            acc1 += ((mm >> 2) & 1) ? -v : v;
            acc2 += ((mm >> 1) & 1) ? -v : v;
            acc3 += ( mm       & 1) ? -v : v;
        }
        A[0][jj][kk] = acc0; A[1][jj][kk] = acc1;
        A[2][jj][kk] = acc2; A[3][jj][kk] = acc3;
    }
    __syncthreads();

    // ---- closed-form coefficient expansion: 16 signed terms each ----
    for (int idx = tid; idx < 324; idx += 128) {
        const int q = idx >> 2, w = idx & 3;
        const int t0 = q / 27, t1 = (q / 9) % 3, t2 = (q / 3) % 3, t3 = q % 3;
        int smask = 0, cmask = 0;
        if (t0 == 2) smask |= 8; else if (t0 == 1) cmask |= 8;
        if (t1 == 2) smask |= 4; else if (t1 == 1) cmask |= 4;
        if (t2 == 2) smask |= 2; else if (t2 == 1) cmask |= 2;
        if (t3 == 2) smask |= 1; else if (t3 == 1) cmask |= 1;
        float c = 0.f;
        #pragma unroll
        for (int u = 0; u < 16; u++) {
            const float v = A[w][u][u ^ smask];
            c += (__popc(u & cmask) & 1) ? -v : v;
        }
        shc[idx] = c * 0.0625f;   // shc[q*4 + w]
    }
    __syncthreads();

    // ---- main loop (R5 configuration): 4 patches/thread, wire-pair FFMA2 ----
    const int base = blockIdx.x * (128 * P) + tid;

    Trig tg[P];
    #pragma unroll
    for (int i = 0; i < P; i++) tg[i] = load_trig(x, base + i * 128);

    ull a0[P][2], a1[P][2], a2[P][2];

    #pragma unroll
    for (int t0 = 0; t0 < 3; t0++) {
        #pragma unroll
        for (int t1 = 0; t1 < 3; t1++) {
            #pragma unroll
            for (int t2 = 0; t2 < 3; t2++) {
                const int q = ((t0 * 3 + t1) * 3 + t2) * 3;
                const ulonglong2 e0 = ((const ulonglong2*)shc)[q];
                const ulonglong2 e1 = ((const ulonglong2*)shc)[q + 1];
                const ulonglong2 e2 = ((const ulonglong2*)shc)[q + 2];

                #pragma unroll
                for (int i = 0; i < P; i++) {
                    const ull ix = ffma2(e2.x, tg[i].s3, ffma2(e1.x, tg[i].c3, e0.x));
                    const ull iy = ffma2(e2.y, tg[i].s3, ffma2(e1.y, tg[i].c3, e0.y));
                    if (t2 == 0)      { a2[i][0] = ix; a2[i][1] = iy; }
                    else if (t2 == 1) { a2[i][0] = ffma2(ix, tg[i].c2, a2[i][0]);
                                        a2[i][1] = ffma2(iy, tg[i].c2, a2[i][1]); }
                    else              { a2[i][0] = ffma2(ix, tg[i].s2, a2[i][0]);
                                        a2[i][1] = ffma2(iy, tg[i].s2, a2[i][1]); }
                }
            }
            #pragma unroll
            for (int i = 0; i < P; i++) {
                if (t1 == 0)      { a1[i][0] = a2[i][0]; a1[i][1] = a2[i][1]; }
                else if (t1 == 1) { a1[i][0] = ffma2(a2[i][0], tg[i].c1, a1[i][0]);
                                    a1[i][1] = ffma2(a2[i][1], tg[i].c1, a1[i][1]); }
                else              { a1[i][0] = ffma2(a2[i][0], tg[i].s1, a1[i][0]);
                                    a1[i][1] = ffma2(a2[i][1], tg[i].s1, a1[i][1]); }
            }
        }
        #pragma unroll
        for (int i = 0; i < P; i++) {
            if (t0 == 0)      { a0[i][0] = a1[i][0]; a0[i][1] = a1[i][1]; }
            else if (t0 == 1) { a0[i][0] = ffma2(a1[i][0], tg[i].c0, a0[i][0]);
                                a0[i][1] = ffma2(a1[i][1], tg[i].c0, a0[i][1]); }
            else              { a0[i][0] = ffma2(a1[i][0], tg[i].s0, a0[i][0]);
                                a0[i][1] = ffma2(a1[i][1], tg[i].s0, a0[i][1]); }
        }
    }

    #pragma unroll
    for (int i = 0; i < P; i++) {
        float4 o;
        unpack2(a0[i][0], o.x, o.y);
        unpack2(a0[i][1], o.z, o.w);
        ((float4*)out)[base + i * 128] = o;
    }
}

extern "C" void kernel_launch(void* const* d_in, const int* in_sizes, int n_in,
                              void* d_out, int out_size)
{
    const float* x      = (const float*)d_in[0];
    const float* params = (const float*)d_in[1];
    if (n_in >= 2 && in_sizes[0] == 24) {
        params = (const float*)d_in[0];
        x      = (const float*)d_in[1];
    }
    float* out = (float*)d_out;

    // 802816 patches / (128 threads * 4 patches) = 1568 blocks exactly
    quanv_fused_kernel<<<1568, 128>>>(x, params, out);
}

// round 10
// speedup vs baseline: 1.3824x; 1.3824x over previous
#include <cuda_runtime.h>

// ---------------------------------------------------------------------------
// Quanvolution filter, algebraically collapsed:
//   <Z_w>(patch) = sum_{t in {I,C,S}^4} coef[w][t] * prod_i f_{t_i}(x_i)
// f_I = 1, f_C = cos(x_i), f_S = sin(x_i).  coef depends only on params.
//
// Two kernels:
//  - quanv_setup_kernel: 1 block / 128 thr, 3 barriers. Basis columns are
//    simulated register-resident (static CNOT perm), A_w = Re(W^H Z_w W),
//    closed-form 16-term coefficient expansion. Target ~1us.
//  - quanv_main_kernel: the measured-best R5 loop: 4 patches/thread,
//    wire-pair-packed f32x2 FFMA2 chains, coefficients broadcast from shared.
// ---------------------------------------------------------------------------

typedef unsigned long long ull;

// coef interleaved by wire: g_coef4[q*4 + w], q = ((t0*3+t1)*3+t2)*3+t3
__device__ __align__(16) float g_coef4[324];

struct cplx { float re, im; };

__device__ __forceinline__ int cnot_perm(int m) {
    m ^= (m & 1) ? 8 : 0;   // f30
    m ^= (m & 2) ? 1 : 0;   // f23
    m ^= (m & 4) ? 2 : 0;   // f12
    m ^= (m & 8) ? 4 : 0;   // f01
    return m;
}

__global__ void quanv_setup_kernel(const float* __restrict__ params)
{
    __shared__ float Gr[8][4];
    __shared__ float Gi[8][4];
    __shared__ float Wr[16][16];  // W[m][j]
    __shared__ float Wi[16][16];
    __shared__ float A[4][16][16];

    const int tid = threadIdx.x;

    // Phase 0: gate matrices G = RX(p2) RZ(p1) RY(p0), one per thread
    if (tid < 8) {
        const float a = params[tid * 3 + 0] * 0.5f;
        const float b = params[tid * 3 + 1] * 0.5f;
        const float c = params[tid * 3 + 2] * 0.5f;
        float ca, sa, cb, sb, cc, sc;
        __sincosf(a, &sa, &ca);
        __sincosf(b, &sb, &cb);
        __sincosf(c, &sc, &cc);
        const float m00r =  cb * ca, m00i = -sb * ca;
        const float m01r = -cb * sa, m01i =  sb * sa;
        const float m10r =  cb * sa, m10i =  sb * sa;
        const float m11r =  cb * ca, m11i =  sb * ca;
        Gr[tid][0] = cc * m00r + sc * m10i;  Gi[tid][0] = cc * m00i - sc * m10r;
        Gr[tid][1] = cc * m01r + sc * m11i;  Gi[tid][1] = cc * m01i - sc * m11r;
        Gr[tid][2] = cc * m10r + sc * m00i;  Gi[tid][2] = cc * m10i - sc * m00r;
        Gr[tid][3] = cc * m11r + sc * m01i;  Gi[tid][3] = cc * m11i - sc * m01r;
    }
    __syncthreads();

    // Phase 1: 16 threads, each simulates basis column j fully in registers.
    if (tid < 16) {
        cplx s[16];
        #pragma unroll
        for (int m = 0; m < 16; m++) s[m] = { 0.f, 0.f };
        s[tid] = { 1.f, 0.f };

        #pragma unroll
        for (int l = 0; l < 2; l++) {
            #pragma unroll
            for (int w = 0; w < 4; w++) {
                const int g = l * 4 + w;
                const float g00r = Gr[g][0], g00i = Gi[g][0];
                const float g01r = Gr[g][1], g01i = Gi[g][1];
                const float g10r = Gr[g][2], g10i = Gi[g][2];
                const float g11r = Gr[g][3], g11i = Gi[g][3];
                const int mask = 8 >> w;
                #pragma unroll
                for (int m = 0; m < 16; m++) {
                    if (m & mask) continue;
                    const cplx s0 = s[m], s1 = s[m | mask];
                    s[m].re        = g00r * s0.re - g00i * s0.im + g01r * s1.re - g01i * s1.im;
                    s[m].im        = g00r * s0.im + g00i * s0.re + g01r * s1.im + g01i * s1.re;
                    s[m | mask].re = g10r * s0.re - g10i * s0.im + g11r * s1.re - g11i * s1.im;
                    s[m | mask].im = g10r * s0.im + g10i * s0.re + g11r * s1.im + g11i * s1.re;
                }
            }
            // composed CNOT-ring permutation (static): new[m] = old[perm(m)]
            cplx t[16];
            #pragma unroll
            for (int m = 0; m < 16; m++) t[m] = s[cnot_perm(m)];
            #pragma unroll
            for (int m = 0; m < 16; m++) s[m] = t[m];
        }
        #pragma unroll
        for (int m = 0; m < 16; m++) { Wr[m][tid] = s[m].re; Wi[m][tid] = s[m].im; }
    }
    __syncthreads();

    // Phase 2: A_w[j][k] = sum_m z_w(m) Re(conj(W[m,j]) W[m,k]); 2 entries/thread
    #pragma unroll
    for (int k = 0; k < 2; k++) {
        const int e = tid + k * 128;
        const int jj = e >> 4, kk = e & 15;
        float acc0 = 0.f, acc1 = 0.f, acc2 = 0.f, acc3 = 0.f;
        #pragma unroll
        for (int mm = 0; mm < 16; mm++) {
            const float v = Wr[mm][jj] * Wr[mm][kk] + Wi[mm][jj] * Wi[mm][kk];
            acc0 += ((mm >> 3) & 1) ? -v : v;
            acc1 += ((mm >> 2) & 1) ? -v : v;
            acc2 += ((mm >> 1) & 1) ? -v : v;
            acc3 += ( mm       & 1) ? -v : v;
        }
        A[0][jj][kk] = acc0; A[1][jj][kk] = acc1;
        A[2][jj][kk] = acc2; A[3][jj][kk] = acc3;
    }
    __syncthreads();

    // Phase 3: closed-form coefficient expansion (16 signed terms each)
    for (int idx = tid; idx < 324; idx += 128) {
        const int q = idx >> 2, w = idx & 3;
        const int t0 = q / 27, t1 = (q / 9) % 3, t2 = (q / 3) % 3, t3 = q % 3;
        int smask = 0, cmask = 0;
        if (t0 == 2) smask |= 8; else if (t0 == 1) cmask |= 8;
        if (t1 == 2) smask |= 4; else if (t1 == 1) cmask |= 4;
        if (t2 == 2) smask |= 2; else if (t2 == 1) cmask |= 2;
        if (t3 == 2) smask |= 1; else if (t3 == 1) cmask |= 1;
        float c = 0.f;
        #pragma unroll
        for (int u = 0; u < 16; u++) {
            const float v = A[w][u][u ^ smask];
            c += (__popc(u & cmask) & 1) ? -v : v;
        }
        g_coef4[idx] = c * 0.0625f;
    }
}

// ---------------------------------------------------------------------------
// Packed f32x2 helpers (Blackwell sm_100+).
// ---------------------------------------------------------------------------
__device__ __forceinline__ ull ffma2(ull a, ull b, ull c) {
    ull d;
    asm("fma.rn.f32x2 %0, %1, %2, %3;" : "=l"(d) : "l"(a), "l"(b), "l"(c));
    return d;
}
__device__ __forceinline__ ull pack2(float x) {
    ull d;
    asm("mov.b64 %0, {%1, %1};" : "=l"(d) : "f"(x));
    return d;
}
__device__ __forceinline__ ull pack2f(float x, float y) {
    ull d;
    asm("mov.b64 %0, {%1, %2};" : "=l"(d) : "f"(x), "f"(y));
    return d;
}
__device__ __forceinline__ void unpack2(ull v, float& lo, float& hi) {
    asm("mov.b64 {%0, %1}, %2;" : "=f"(lo), "=f"(hi) : "l"(v));
}

struct Trig { ull c0, s0, c1, s1, c2, s2, c3, s3; };

__device__ __forceinline__ Trig load_trig(const float* __restrict__ x, int pidx)
{
    const int b   = pidx / 196;
    const int p   = pidx - b * 196;
    const int r   = p / 14;
    const int col = p - r * 14;
    const float* xp = x + b * 784 + r * 56 + col * 2;
    const float2 top = *(const float2*)xp;
    const float2 bot = *(const float2*)(xp + 28);
    float c0, s0, c1, s1, c2, s2, c3, s3;
    __sincosf(top.x, &s0, &c0);
    __sincosf(top.y, &s1, &c1);
    __sincosf(bot.x, &s2, &c2);
    __sincosf(bot.y, &s3, &c3);
    Trig t;
    t.c0 = pack2(c0); t.s0 = pack2(s0);
    t.c1 = pack2(c1); t.s1 = pack2(s1);
    t.c2 = pack2(c2); t.s2 = pack2(s2);
    t.c3 = pack2(c3); t.s3 = pack2(s3);
    return t;
}

// ---------------------------------------------------------------------------
// Main kernel (R5 config, measured 14.4us): 128 threads/block, 4 patches/thr.
// sh[2*q] = packed coef (w0,w1), sh[2*q+1] = packed (w2,w3).
// ---------------------------------------------------------------------------
#define P 4

__global__ void __launch_bounds__(128)
quanv_main_kernel(const float* __restrict__ x, float* __restrict__ out)
{
    __shared__ __align__(16) ull sh[162];
    const int tid = threadIdx.x;

    if (tid < 81) {
        const float4 v = ((const float4*)g_coef4)[tid];
        sh[2 * tid]     = pack2f(v.x, v.y);
        sh[2 * tid + 1] = pack2f(v.z, v.w);
    }
    __syncthreads();

    const int base = blockIdx.x * (128 * P) + tid;

    Trig tg[P];
    #pragma unroll
    for (int i = 0; i < P; i++) tg[i] = load_trig(x, base + i * 128);

    ull a0[P][2], a1[P][2], a2[P][2];

    #pragma unroll
    for (int t0 = 0; t0 < 3; t0++) {
        #pragma unroll
        for (int t1 = 0; t1 < 3; t1++) {
            #pragma unroll
            for (int t2 = 0; t2 < 3; t2++) {
                const int q = ((t0 * 3 + t1) * 3 + t2) * 3;
                const ulonglong2 e0 = ((const ulonglong2*)sh)[q];
                const ulonglong2 e1 = ((const ulonglong2*)sh)[q + 1];
                const ulonglong2 e2 = ((const ulonglong2*)sh)[q + 2];

                #pragma unroll
                for (int i = 0; i < P; i++) {
                    const ull ix = ffma2(e2.x, tg[i].s3, ffma2(e1.x, tg[i].c3, e0.x));
                    const ull iy = ffma2(e2.y, tg[i].s3, ffma2(e1.y, tg[i].c3, e0.y));
                    if (t2 == 0)      { a2[i][0] = ix; a2[i][1] = iy; }
                    else if (t2 == 1) { a2[i][0] = ffma2(ix, tg[i].c2, a2[i][0]);
                                        a2[i][1] = ffma2(iy, tg[i].c2, a2[i][1]); }
                    else              { a2[i][0] = ffma2(ix, tg[i].s2, a2[i][0]);
                                        a2[i][1] = ffma2(iy, tg[i].s2, a2[i][1]); }
                }
            }
            #pragma unroll
            for (int i = 0; i < P; i++) {
                if (t1 == 0)      { a1[i][0] = a2[i][0]; a1[i][1] = a2[i][1]; }
                else if (t1 == 1) { a1[i][0] = ffma2(a2[i][0], tg[i].c1, a1[i][0]);
                                    a1[i][1] = ffma2(a2[i][1], tg[i].c1, a1[i][1]); }
                else              { a1[i][0] = ffma2(a2[i][0], tg[i].s1, a1[i][0]);
                                    a1[i][1] = ffma2(a2[i][1], tg[i].s1, a1[i][1]); }
            }
        }
        #pragma unroll
        for (int i = 0; i < P; i++) {
            if (t0 == 0)      { a0[i][0] = a1[i][0]; a0[i][1] = a1[i][1]; }
            else if (t0 == 1) { a0[i][0] = ffma2(a1[i][0], tg[i].c0, a0[i][0]);
                                a0[i][1] = ffma2(a1[i][1], tg[i].c0, a0[i][1]); }
            else              { a0[i][0] = ffma2(a1[i][0], tg[i].s0, a0[i][0]);
                                a0[i][1] = ffma2(a1[i][1], tg[i].s0, a0[i][1]); }
        }
    }

    #pragma unroll
    for (int i = 0; i < P; i++) {
        float4 o;
        unpack2(a0[i][0], o.x, o.y);
        unpack2(a0[i][1], o.z, o.w);
        ((float4*)out)[base + i * 128] = o;
    }
}

extern "C" void kernel_launch(void* const* d_in, const int* in_sizes, int n_in,
                              void* d_out, int out_size)
{
    const float* x      = (const float*)d_in[0];
    const float* params = (const float*)d_in[1];
    if (n_in >= 2 && in_sizes[0] == 24) {
        params = (const float*)d_in[0];
        x      = (const float*)d_in[1];
    }
    float* out = (float*)d_out;

    quanv_setup_kernel<<<1, 128>>>(params);
    // 802816 patches / (128 threads * 4 patches) = 1568 blocks exactly
    quanv_main_kernel<<<1568, 128>>>(x, out);
}